// round 10
// baseline (speedup 1.0000x reference)
#include <cuda_runtime.h>
#include <cuda_bf16.h>
#include <cuda_fp16.h>
#include <math.h>
#include <stdint.h>

#define NN    50000
#define FEAT  128
#define HID   256
#define K0    160        // layer-0 K (129 live -> 132 used) padded to 160
#define NE    800000
#define NSUB  512
#define SUBSZ 64
#define MTOT  (NSUB*SUBSZ)

#define SCAN_B 256
#define NBLK   ((NN + SCAN_B - 1) / SCAN_B)   // 196

// ---------------- scratch (device globals; no allocation allowed) ----------------
__device__ __align__(16) __nv_bfloat16  g_B0 [NN*K0];    // bf16 h0
__device__ __align__(16) __nv_bfloat16  g_BA [NN*HID];   // bf16 h (layers)
__device__ __align__(16) __nv_bfloat16  g_BB [NN*HID];
__device__ __align__(16) __half         g_W0h[K0*HID];   // fp16 zero-padded W0
__device__ __align__(16) __half         g_W1h[HID*HID];
__device__ __align__(16) __half         g_W2h[HID*HID];
__device__ __align__(16) float          g_Z  [NSUB*4*HID];
// CSR scratch
__device__ int   g_deg [NN];
__device__ int   g_cur [NN];
__device__ int   g_off [NN+1];
__device__ int   g_bsum[NBLK];
__device__ int   g_csrc[NE];
__device__ float g_cw  [NE];

__device__ __forceinline__ __nv_bfloat16* gbuf16(int id){
    switch(id){
        case 0: return g_B0;
        case 1: return g_BA;
        default: return g_BB;
    }
}

// ---------------- setup ----------------
__global__ void build_h0(const float* __restrict__ x){
    int idx = blockIdx.x*blockDim.x + threadIdx.x;
    const int total = NN*K0;
    for (; idx < total; idx += gridDim.x*blockDim.x){
        int i = idx / K0;
        int c = idx - i*K0;
        g_B0[idx] = (c < FEAT) ? __float2bfloat16(x[i*FEAT + c]) : __float2bfloat16(0.f);
    }
}

__global__ void scatter_batch(const int* __restrict__ batches){
    int m = blockIdx.x*blockDim.x + threadIdx.x;
    if (m < MTOT) g_B0[(size_t)batches[m]*K0 + FEAT] = __float2bfloat16(1.0f);
}

__global__ void build_w0h(const float* __restrict__ W0){
    int idx = blockIdx.x*blockDim.x + threadIdx.x;
    if (idx < K0*HID){
        int r = idx / HID;
        int c = idx - r*HID;
        g_W0h[idx] = (r < FEAT+1) ? __float2half(W0[r*HID + c]) : __float2half(0.f);
    }
}

__global__ void build_wh(const float* __restrict__ W, int sel){
    __half* dst = (sel == 1) ? g_W1h : g_W2h;
    int i = blockIdx.x*blockDim.x + threadIdx.x;
    if (i < HID*HID) dst[i] = __float2half(W[i]);
}

// ---------------- CSR build ----------------
__global__ void zero_degcur(){
    int i = blockIdx.x*blockDim.x + threadIdx.x;
    if (i < NN){ g_deg[i] = 0; g_cur[i] = 0; }
}

__global__ void hist_dst(const int* __restrict__ dst){
    int e = blockIdx.x*blockDim.x + threadIdx.x;
    if (e < NE) atomicAdd(&g_deg[dst[e]], 1);
}

__global__ void scan_block(){
    __shared__ int sh[SCAN_B];
    int i = blockIdx.x*SCAN_B + threadIdx.x;
    int v = (i < NN) ? g_deg[i] : 0;
    sh[threadIdx.x] = v;
    __syncthreads();
    #pragma unroll
    for (int off = 1; off < SCAN_B; off <<= 1){
        int add = (threadIdx.x >= off) ? sh[threadIdx.x - off] : 0;
        __syncthreads();
        sh[threadIdx.x] += add;
        __syncthreads();
    }
    if (i < NN) g_off[i] = sh[threadIdx.x] - v;
    if (threadIdx.x == SCAN_B-1) g_bsum[blockIdx.x] = sh[SCAN_B-1];
}

__global__ void scan_bsums(){
    __shared__ int sh[256];
    int t = threadIdx.x;
    int v = (t < NBLK) ? g_bsum[t] : 0;
    sh[t] = v;
    __syncthreads();
    #pragma unroll
    for (int off = 1; off < 256; off <<= 1){
        int add = (t >= off) ? sh[t - off] : 0;
        __syncthreads();
        sh[t] += add;
        __syncthreads();
    }
    if (t < NBLK) g_bsum[t] = sh[t] - v;
}

__global__ void scan_add(){
    int i = blockIdx.x*SCAN_B + threadIdx.x;
    if (i < NN) g_off[i] += g_bsum[blockIdx.x];
    if (i == 0) g_off[NN] = NE;
}

__global__ void csr_scatter(const int* __restrict__ src, const int* __restrict__ dst,
                            const float* __restrict__ ew){
    int e = blockIdx.x*blockDim.x + threadIdx.x;
    if (e < NE){
        int d = dst[e];
        int pos = g_off[d] + atomicAdd(&g_cur[d], 1);
        g_csrc[pos] = src[e];
        g_cw[pos]   = ew[e];
    }
}

// ---------------- helpers ----------------
__device__ __forceinline__ void facc(float4& a, float w, uint2 u){
    float2 f0 = __bfloat1622float2(*(__nv_bfloat162*)&u.x);
    float2 f1 = __bfloat1622float2(*(__nv_bfloat162*)&u.y);
    a.x += w*f0.x; a.y += w*f0.y; a.z += w*f1.x; a.w += w*f1.y;
}
__device__ __forceinline__ uint2 f4toh4(float4 a){
    __half2 lo = __floats2half2_rn(a.x, a.y);
    __half2 hi = __floats2half2_rn(a.z, a.w);
    return make_uint2(*(uint32_t*)&lo, *(uint32_t*)&hi);
}
__device__ __forceinline__ uint32_t sptr(const void* p){
    return (uint32_t)__cvta_generic_to_shared(p);
}
__device__ __forceinline__ void cpa16(uint32_t smem, const void* g){
    asm volatile("cp.async.cg.shared.global [%0], [%1], 16;"
                 :: "r"(smem), "l"(g) : "memory");
}
#define CP_COMMIT() asm volatile("cp.async.commit_group;" ::: "memory")
#define CP_WAIT0()  asm volatile("cp.async.wait_group 0;" ::: "memory")

__device__ __forceinline__ void ldsm4(uint32_t& r0,uint32_t& r1,uint32_t& r2,uint32_t& r3, uint32_t a){
    asm volatile("ldmatrix.sync.aligned.m8n8.x4.shared.b16 {%0,%1,%2,%3},[%4];"
                 : "=r"(r0),"=r"(r1),"=r"(r2),"=r"(r3) : "r"(a));
}
__device__ __forceinline__ void ldsm4t(uint32_t& r0,uint32_t& r1,uint32_t& r2,uint32_t& r3, uint32_t a){
    asm volatile("ldmatrix.sync.aligned.m8n8.x4.trans.shared.b16 {%0,%1,%2,%3},[%4];"
                 : "=r"(r0),"=r"(r1),"=r"(r2),"=r"(r3) : "r"(a));
}
__device__ __forceinline__ void mma16816h(float* c, const uint32_t* a, uint32_t b0, uint32_t b1){
    asm volatile("mma.sync.aligned.m16n8k16.row.col.f32.f16.f16.f32 "
                 "{%0,%1,%2,%3},{%4,%5,%6,%7},{%8,%9},{%0,%1,%2,%3};"
                 : "+f"(c[0]),"+f"(c[1]),"+f"(c[2]),"+f"(c[3])
                 : "r"(a[0]),"r"(a[1]),"r"(a[2]),"r"(a[3]),"r"(b0),"r"(b1));
}

// ---------------- fused GIN layer: gather + GEMM + bias + relu ----------------
// CTA: 64 node-rows x full N=256. Phase 1: CSR gather -> Ash fp16 (stride K+8).
// Phase 2: mma, B double-buffered via cp.async.
#define BLN 264    // Bsh row stride (halves) for N=256

template<int K>
__global__ __launch_bounds__(256, 2)
void fused_layer(int hsel, int wsel, const float* __restrict__ bias,
                 const float* __restrict__ eps, int ei, int osel,
                 int w4r, int w4p){
    constexpr int AL = K + 8;
    extern __shared__ __half smem[];
    __half* Ash = smem;               // 64*AL
    __half* Bsh = smem + 64*AL;       // 2*32*BLN

    const __nv_bfloat16* h = gbuf16(hsel);
    const __half* Wh = (wsel == 0) ? g_W0h : (wsel == 1) ? g_W1h : g_W2h;
    __nv_bfloat16* out = gbuf16(osel);

    const int t = threadIdx.x;
    const int warp = t >> 5, lane = t & 31;
    const int rows0 = blockIdx.x*64;

    auto prefetchB = [&](int ks, int buf){
        const int k0 = ks*32;
        #pragma unroll
        for (int s=0;s<4;s++){
            int c = t + s*256;
            int r = c >> 5, seg = c & 31;
            uint32_t dst = sptr(&Bsh[buf*32*BLN + r*BLN + seg*8]);
            cpa16(dst, Wh + (size_t)(k0 + r)*HID + seg*8);
        }
    };

    // B stage 0 in flight before the gather phase
    prefetchB(0, 0); CP_COMMIT();

    // ---------------- phase 1: gather 8 rows per warp ----------------
    {
        const float ep = 1.0f + eps[ei];
        const bool a0 = (lane      < w4r);
        const bool a1 = (lane + 32 < w4r);
        for (int rr = 0; rr < 8; rr++){
            int r = warp*8 + rr;
            int n = rows0 + r;
            float4 acc0 = make_float4(0.f,0.f,0.f,0.f);
            float4 acc1 = make_float4(0.f,0.f,0.f,0.f);
            if (n < NN){
                int s0 = g_off[n], s1 = g_off[n+1];
                int e = s0;
                for (; e + 4 <= s1; e += 4){
                    int   si[4]; float wi[4];
                    #pragma unroll
                    for (int j=0;j<4;j++){
                        si[j] = __ldg(&g_csrc[e+j]);
                        wi[j] = __ldg(&g_cw[e+j]);
                    }
                    uint2 u0[4], u1[4];
                    #pragma unroll
                    for (int j=0;j<4;j++){
                        const uint2* hs = (const uint2*)(h + (size_t)si[j]*K);
                        if (a0) u0[j] = __ldg(&hs[lane]);
                        if (a1) u1[j] = __ldg(&hs[lane+32]);
                    }
                    #pragma unroll
                    for (int j=0;j<4;j++){
                        if (a0) facc(acc0, wi[j], u0[j]);
                        if (a1) facc(acc1, wi[j], u1[j]);
                    }
                }
                for (; e < s1; e++){
                    int   s = __ldg(&g_csrc[e]);
                    float w = __ldg(&g_cw[e]);
                    const uint2* hs = (const uint2*)(h + (size_t)s*K);
                    if (a0){ uint2 u = __ldg(&hs[lane]);    facc(acc0, w, u); }
                    if (a1){ uint2 u = __ldg(&hs[lane+32]); facc(acc1, w, u); }
                }
                const uint2* hn = (const uint2*)(h + (size_t)n*K);
                if (a0){ uint2 u = __ldg(&hn[lane]);    facc(acc0, ep, u); }
                if (a1){ uint2 u = __ldg(&hn[lane+32]); facc(acc1, ep, u); }
            }
            // store row to Ash (zeros for OOB rows / pad cols)
            if (a0) *(uint2*)&Ash[r*AL + lane*4] = f4toh4(acc0);
            if (a1) *(uint2*)&Ash[r*AL + (lane+32)*4] = f4toh4(acc1);
            else if (lane + 32 < w4p) *(uint2*)&Ash[r*AL + (lane+32)*4] = make_uint2(0u,0u);
        }
    }
    __syncthreads();   // Ash ready

    // ---------------- phase 2: mma ----------------
    const int wm = warp >> 2, wn = warp & 3;   // 2 x 4 warps, warp tile 32 x 64

    float acc[2][8][4];
    #pragma unroll
    for (int i=0;i<2;i++)
        #pragma unroll
        for (int j=0;j<8;j++)
            #pragma unroll
            for (int q=0;q<4;q++) acc[i][j][q]=0.f;

    const int KS = K/32;
    int buf = 0;
    for (int ks=0; ks<KS; ks++){
        CP_WAIT0();
        __syncthreads();
        if (ks+1 < KS){ prefetchB(ks+1, buf^1); CP_COMMIT(); }
        #pragma unroll
        for (int hh=0; hh<2; hh++){
            const int arow = wm*32 + (lane & 15);
            const int acol = ks*32 + hh*16 + (lane >> 4)*8;
            uint32_t aA = sptr(&Ash[0]) + (uint32_t)((arow*AL + acol)*2);
            const int brow = hh*16 + (lane & 15);
            const int bcol = wn*64 + (lane >> 4)*8;
            uint32_t bA = sptr(&Bsh[buf*32*BLN]) + (uint32_t)((brow*BLN + bcol)*2);

            uint32_t A_[2][4], B[8][2];
            #pragma unroll
            for (int mi=0; mi<2; mi++)
                ldsm4(A_[mi][0],A_[mi][1],A_[mi][2],A_[mi][3], aA + (uint32_t)(mi*16*AL*2));
            #pragma unroll
            for (int np=0; np<4; np++)
                ldsm4t(B[2*np][0],B[2*np][1],B[2*np+1][0],B[2*np+1][1],
                       bA + (uint32_t)(np*16*2));
            #pragma unroll
            for (int mi=0; mi<2; mi++)
                #pragma unroll
                for (int ni=0; ni<8; ni++)
                    mma16816h(acc[mi][ni], A_[mi], B[ni][0], B[ni][1]);
        }
        buf ^= 1;
    }

    // epilogue: bias + relu, bf16 stores
    const int gid = lane >> 2, tig = lane & 3;
    #pragma unroll
    for (int ni=0; ni<8; ni++){
        int c = wn*64 + ni*8 + tig*2;
        float2 bb = *(const float2*)(bias + c);
        #pragma unroll
        for (int mi=0; mi<2; mi++){
            int r = rows0 + wm*32 + mi*16 + gid;
            if (r < NN){
                __nv_bfloat162 o = __floats2bfloat162_rn(
                    fmaxf(acc[mi][ni][0] + bb.x, 0.f),
                    fmaxf(acc[mi][ni][1] + bb.y, 0.f));
                *(__nv_bfloat162*)(out + (size_t)r*HID + c) = o;
            }
            int r2 = r + 8;
            if (r2 < NN){
                __nv_bfloat162 o = __floats2bfloat162_rn(
                    fmaxf(acc[mi][ni][2] + bb.x, 0.f),
                    fmaxf(acc[mi][ni][3] + bb.y, 0.f));
                *(__nv_bfloat162*)(out + (size_t)r2*HID + c) = o;
            }
        }
    }
}

// ---------------- multipool (bf16 input) ----------------
__global__ void pool_kernel(const int* __restrict__ batches){
    const __nv_bfloat16* h = g_BA;   // final layer output
    __shared__ int idxs[SUBSZ];
    int t = threadIdx.x, b = blockIdx.x;
    if (t < SUBSZ) idxs[t] = batches[b*SUBSZ + t];
    __syncthreads();
    float s = 0.f, mn = 3.4e38f, mx = -3.4e38f;
    #pragma unroll 8
    for (int m = 0; m < SUBSZ; m++){
        float v = __bfloat162float(h[(size_t)idxs[m]*HID + t]);
        s += v; mn = fminf(mn, v); mx = fmaxf(mx, v);
    }
    float* z = g_Z + (size_t)b*4*HID;
    z[t]         = s;
    z[HID + t]   = s * (1.0f/SUBSZ);
    z[2*HID + t] = mn;
    z[3*HID + t] = mx;
}

// ---------------- readout + BCE ----------------
__global__ void zero_out(float* out){
    if (threadIdx.x == 0 && blockIdx.x == 0) out[0] = 0.f;
}

__global__ __launch_bounds__(256)
void readout8(const float* __restrict__ Wr1, const float* __restrict__ br1,
              const float* __restrict__ Wr2, const float* __restrict__ br2,
              const float* __restrict__ labels, float* out){
    const int b0 = blockIdx.x*8;
    __shared__ float z[8*4*HID];
    int t = threadIdx.x;
    const float4* zg = (const float4*)(g_Z + (size_t)b0*4*HID);
    #pragma unroll
    for (int j = t; j < 8*4*HID/4; j += 256)
        ((float4*)z)[j] = zg[j];
    __syncthreads();

    float bb = br1[t];
    float acc[8];
    #pragma unroll
    for (int j=0;j<8;j++) acc[j] = bb;

    #pragma unroll 8
    for (int k=0;k<4*HID;k++){
        float w = Wr1[(size_t)k*HID + t];
        #pragma unroll
        for (int j=0;j<8;j++) acc[j] += z[j*4*HID + k]*w;
    }
    __syncthreads();
    float wr2 = Wr2[t];
    #pragma unroll
    for (int j=0;j<8;j++) z[j*HID + t] = fmaxf(acc[j], 0.f)*wr2;
    __syncthreads();

    int w = t >> 5, lane = t & 31;
    float s = 0.f;
    #pragma unroll
    for (int q=0;q<8;q++) s += z[w*HID + lane + q*32];
    #pragma unroll
    for (int off=16; off>0; off>>=1) s += __shfl_xor_sync(0xffffffffu, s, off);
    if (lane == 0){
        float p = s + br2[0];
        float l = labels[b0 + w];
        float term = fmaxf(p, 0.f) - p*l + log1pf(expf(-fabsf(p)));
        atomicAdd(out, term * (1.0f/NSUB));
    }
}

// ---------------- launch ----------------
static cudaStream_t g_s2 = nullptr;
static cudaEvent_t  g_evFork = nullptr, g_evJoin = nullptr;

#define SMEM_FUSED(K) ((64*((K)+8) + 2*32*BLN) * 2)

extern "C" void kernel_launch(void* const* d_in, const int* in_sizes, int n_in,
                              void* d_out, int out_size){
    const float* x       = (const float*)d_in[0];
    const int*   esrc    = (const int*)  d_in[1];
    const int*   edst    = (const int*)  d_in[2];
    const float* ew      = (const float*)d_in[3];
    const int*   batches = (const int*)  d_in[4];
    const float* labels  = (const float*)d_in[6];
    const float* W0      = (const float*)d_in[7];
    const float* b0      = (const float*)d_in[8];
    const float* W1      = (const float*)d_in[9];
    const float* b1      = (const float*)d_in[10];
    const float* W2      = (const float*)d_in[11];
    const float* b2      = (const float*)d_in[12];
    const float* eps     = (const float*)d_in[13];
    const float* Wr1     = (const float*)d_in[14];
    const float* br1     = (const float*)d_in[15];
    const float* Wr2     = (const float*)d_in[16];
    const float* br2     = (const float*)d_in[17];
    float* out = (float*)d_out;

    if (!g_s2){
        cudaStreamCreateWithFlags(&g_s2, cudaStreamNonBlocking);
        cudaEventCreateWithFlags(&g_evFork, cudaEventDisableTiming);
        cudaEventCreateWithFlags(&g_evJoin, cudaEventDisableTiming);
        cudaFuncSetAttribute(fused_layer<K0>,  cudaFuncAttributeMaxDynamicSharedMemorySize, SMEM_FUSED(K0));
        cudaFuncSetAttribute(fused_layer<HID>, cudaFuncAttributeMaxDynamicSharedMemorySize, SMEM_FUSED(HID));
    }

    cudaEventRecord(g_evFork, 0);
    cudaStreamWaitEvent(g_s2, g_evFork, 0);

    // main stream: input prep + weight conversion
    build_h0<<<4096, 256>>>(x);
    scatter_batch<<<(MTOT+255)/256, 256>>>(batches);
    build_w0h<<<(K0*HID+255)/256, 256>>>(W0);
    build_wh<<<(HID*HID+255)/256, 256>>>(W1, 1);
    build_wh<<<(HID*HID+255)/256, 256>>>(W2, 2);

    // side stream: CSR build (by dst)
    zero_degcur<<<(NN+255)/256, 256, 0, g_s2>>>();
    hist_dst<<<(NE+255)/256, 256, 0, g_s2>>>(edst);
    scan_block<<<NBLK, SCAN_B, 0, g_s2>>>();
    scan_bsums<<<1, 256, 0, g_s2>>>();
    scan_add<<<NBLK, SCAN_B, 0, g_s2>>>();
    csr_scatter<<<(NE+255)/256, 256, 0, g_s2>>>(esrc, edst, ew);

    cudaEventRecord(g_evJoin, g_s2);
    cudaStreamWaitEvent(0, g_evJoin, 0);

    const int fusedGrid = (NN + 63) / 64;   // 782

    // layer 0: 132 live cols (33 units), pad to 160 (40 units)
    fused_layer<K0><<<fusedGrid, 256, SMEM_FUSED(K0)>>>(0, 0, b0, eps, 0, 1, 33, 40);
    // layer 1
    fused_layer<HID><<<fusedGrid, 256, SMEM_FUSED(HID)>>>(1, 1, b1, eps, 1, 2, 64, 64);
    // layer 2
    fused_layer<HID><<<fusedGrid, 256, SMEM_FUSED(HID)>>>(2, 2, b2, eps, 2, 1, 64, 64);

    pool_kernel<<<NSUB, HID>>>(batches);
    zero_out<<<1, 32>>>(out);
    readout8<<<NSUB/8, 256>>>(Wr1, br1, Wr2, br2, labels, out);
}

// round 11
// speedup vs baseline: 1.0588x; 1.0588x over previous
#include <cuda_runtime.h>
#include <cuda_bf16.h>
#include <cuda_fp16.h>
#include <math.h>
#include <stdint.h>

#define NN    50000
#define FEAT  128
#define HID   256
#define K0    160        // layer-0 K (129 live -> 132 used) padded to 160
#define NE    800000
#define NSUB  512
#define SUBSZ 64
#define MTOT  (NSUB*SUBSZ)

#define SCAN_B 256
#define NBLK   ((NN + SCAN_B - 1) / SCAN_B)   // 196

// ---------------- scratch (device globals; no allocation allowed) ----------------
__device__ __align__(16) __half         g_MSG[NN*HID];   // fp16 GEMM A (160-col view for L0)
__device__ __align__(16) __nv_bfloat16  g_B0 [NN*K0];    // bf16 h0
__device__ __align__(16) __nv_bfloat16  g_BA [NN*HID];   // bf16 h (layers)
__device__ __align__(16) __nv_bfloat16  g_BB [NN*HID];
__device__ __align__(16) __half         g_W0h[K0*HID];   // fp16 zero-padded W0
__device__ __align__(16) __half         g_W1h[HID*HID];
__device__ __align__(16) __half         g_W2h[HID*HID];
__device__ __align__(16) float          g_Z  [NSUB*4*HID];
// CSR scratch
__device__ int   g_deg [NN];
__device__ int   g_cur [NN];
__device__ int   g_off [NN+1];
__device__ int   g_bsum[NBLK];
__device__ int   g_csrc[NE];
__device__ float g_cw  [NE];

__device__ __forceinline__ __nv_bfloat16* gbuf16(int id){
    switch(id){
        case 0: return g_B0;
        case 1: return g_BA;
        default: return g_BB;
    }
}

// ---------------- setup ----------------
__global__ void build_h0(const float* __restrict__ x){
    int idx = blockIdx.x*blockDim.x + threadIdx.x;
    const int total = NN*K0;
    for (; idx < total; idx += gridDim.x*blockDim.x){
        int i = idx / K0;
        int c = idx - i*K0;
        g_B0[idx] = (c < FEAT) ? __float2bfloat16(x[i*FEAT + c]) : __float2bfloat16(0.f);
    }
}

__global__ void scatter_batch(const int* __restrict__ batches){
    int m = blockIdx.x*blockDim.x + threadIdx.x;
    if (m < MTOT) g_B0[(size_t)batches[m]*K0 + FEAT] = __float2bfloat16(1.0f);
}

__global__ void build_w0h(const float* __restrict__ W0){
    int idx = blockIdx.x*blockDim.x + threadIdx.x;
    if (idx < K0*HID){
        int r = idx / HID;
        int c = idx - r*HID;
        g_W0h[idx] = (r < FEAT+1) ? __float2half(W0[r*HID + c]) : __float2half(0.f);
    }
}

__global__ void build_wh(const float* __restrict__ W, int sel){
    __half* dst = (sel == 1) ? g_W1h : g_W2h;
    int i = blockIdx.x*blockDim.x + threadIdx.x;
    if (i < HID*HID) dst[i] = __float2half(W[i]);
}

// ---------------- CSR build ----------------
__global__ void zero_degcur(){
    int i = blockIdx.x*blockDim.x + threadIdx.x;
    if (i < NN){ g_deg[i] = 0; g_cur[i] = 0; }
}

__global__ void hist_dst(const int* __restrict__ dst){
    int e = blockIdx.x*blockDim.x + threadIdx.x;
    if (e < NE) atomicAdd(&g_deg[dst[e]], 1);
}

__global__ void scan_block(){
    __shared__ int sh[SCAN_B];
    int i = blockIdx.x*SCAN_B + threadIdx.x;
    int v = (i < NN) ? g_deg[i] : 0;
    sh[threadIdx.x] = v;
    __syncthreads();
    #pragma unroll
    for (int off = 1; off < SCAN_B; off <<= 1){
        int add = (threadIdx.x >= off) ? sh[threadIdx.x - off] : 0;
        __syncthreads();
        sh[threadIdx.x] += add;
        __syncthreads();
    }
    if (i < NN) g_off[i] = sh[threadIdx.x] - v;
    if (threadIdx.x == SCAN_B-1) g_bsum[blockIdx.x] = sh[SCAN_B-1];
}

__global__ void scan_bsums(){
    __shared__ int sh[256];
    int t = threadIdx.x;
    int v = (t < NBLK) ? g_bsum[t] : 0;
    sh[t] = v;
    __syncthreads();
    #pragma unroll
    for (int off = 1; off < 256; off <<= 1){
        int add = (t >= off) ? sh[t - off] : 0;
        __syncthreads();
        sh[t] += add;
        __syncthreads();
    }
    if (t < NBLK) g_bsum[t] = sh[t] - v;
}

__global__ void scan_add(){
    int i = blockIdx.x*SCAN_B + threadIdx.x;
    if (i < NN) g_off[i] += g_bsum[blockIdx.x];
    if (i == 0) g_off[NN] = NE;
}

__global__ void csr_scatter(const int* __restrict__ src, const int* __restrict__ dst,
                            const float* __restrict__ ew){
    int e = blockIdx.x*blockDim.x + threadIdx.x;
    if (e < NE){
        int d = dst[e];
        int pos = g_off[d] + atomicAdd(&g_cur[d], 1);
        g_csrc[pos] = src[e];
        g_cw[pos]   = ew[e];
    }
}

// ---------------- gather: 2 warps per node, edge-unroll x8 ----------------
__device__ __forceinline__ void facc(float4& a, float w, uint2 u){
    float2 f0 = __bfloat1622float2(*(__nv_bfloat162*)&u.x);
    float2 f1 = __bfloat1622float2(*(__nv_bfloat162*)&u.y);
    a.x += w*f0.x; a.y += w*f0.y; a.z += w*f1.x; a.w += w*f1.y;
}
__device__ __forceinline__ uint2 f4toh4(float4 a){
    __half2 lo = __floats2half2_rn(a.x, a.y);
    __half2 hi = __floats2half2_rn(a.z, a.w);
    return make_uint2(*(uint32_t*)&lo, *(uint32_t*)&hi);
}

__global__ __launch_bounds__(256)
void csr_gather(int hsel, const float* __restrict__ eps, int ei, int ld, int w4r, int w4p){
    const __nv_bfloat16* h = gbuf16(hsel);
    int n = blockIdx.x*4 + (threadIdx.x >> 6);   // 4 nodes/block, 2 warps/node
    if (n >= NN) return;
    int lane64 = threadIdx.x & 63;               // column index (uint2 units)
    const bool act = (lane64 < w4r);
    int s0 = g_off[n], s1 = g_off[n+1];

    float4 acc = make_float4(0.f,0.f,0.f,0.f);

    int e = s0;
    for (; e + 8 <= s1; e += 8){
        int   si[8]; float wi[8];
        #pragma unroll
        for (int j=0;j<8;j++){
            si[j] = __ldg(&g_csrc[e+j]);
            wi[j] = __ldg(&g_cw[e+j]);
        }
        uint2 u[8];
        #pragma unroll
        for (int j=0;j<8;j++){
            if (act) u[j] = __ldg(&((const uint2*)(h + (size_t)si[j]*ld))[lane64]);
        }
        #pragma unroll
        for (int j=0;j<8;j++){
            if (act) facc(acc, wi[j], u[j]);
        }
    }
    for (; e < s1; e++){
        int   s = __ldg(&g_csrc[e]);
        float w = __ldg(&g_cw[e]);
        if (act){
            uint2 u = __ldg(&((const uint2*)(h + (size_t)s*ld))[lane64]);
            facc(acc, w, u);
        }
    }

    const float ep = 1.0f + eps[ei];
    uint2* mrow = (uint2*)(g_MSG + (size_t)n*ld);
    if (act){
        uint2 u = __ldg(&((const uint2*)(h + (size_t)n*ld))[lane64]);
        facc(acc, ep, u);
        mrow[lane64] = f4toh4(acc);
    } else if (lane64 < w4p){
        mrow[lane64] = make_uint2(0u, 0u);
    }
}

// ---------------- tensor-core GIN GEMM: outb16 = relu(MSG @ W + b) ------
// pure fp16, BK=32, cp.async double-buffered, 1 sync per kstep.
__device__ __forceinline__ uint32_t sptr(const void* p){
    return (uint32_t)__cvta_generic_to_shared(p);
}
__device__ __forceinline__ void cpa16(uint32_t smem, const void* g, int nbytes){
    asm volatile("cp.async.cg.shared.global [%0], [%1], 16, %2;"
                 :: "r"(smem), "l"(g), "r"(nbytes) : "memory");
}
#define CP_COMMIT() asm volatile("cp.async.commit_group;" ::: "memory")
#define CP_WAIT0()  asm volatile("cp.async.wait_group 0;" ::: "memory")

__device__ __forceinline__ void ldsm4(uint32_t& r0,uint32_t& r1,uint32_t& r2,uint32_t& r3, uint32_t a){
    asm volatile("ldmatrix.sync.aligned.m8n8.x4.shared.b16 {%0,%1,%2,%3},[%4];"
                 : "=r"(r0),"=r"(r1),"=r"(r2),"=r"(r3) : "r"(a));
}
__device__ __forceinline__ void ldsm4t(uint32_t& r0,uint32_t& r1,uint32_t& r2,uint32_t& r3, uint32_t a){
    asm volatile("ldmatrix.sync.aligned.m8n8.x4.trans.shared.b16 {%0,%1,%2,%3},[%4];"
                 : "=r"(r0),"=r"(r1),"=r"(r2),"=r"(r3) : "r"(a));
}
__device__ __forceinline__ void mma16816h(float* c, const uint32_t* a, uint32_t b0, uint32_t b1){
    asm volatile("mma.sync.aligned.m16n8k16.row.col.f32.f16.f16.f32 "
                 "{%0,%1,%2,%3},{%4,%5,%6,%7},{%8,%9},{%0,%1,%2,%3};"
                 : "+f"(c[0]),"+f"(c[1]),"+f"(c[2]),"+f"(c[3])
                 : "r"(a[0]),"r"(a[1]),"r"(a[2]),"r"(a[3]),"r"(b0),"r"(b1));
}

#define ALD2 40    // Ash row stride (halves), BK=32 + pad 8
#define BLD  136   // Bsh row stride (halves)

template<int K>
__global__ __launch_bounds__(256)
void gemm_mma(int wsel, const float* __restrict__ bias, int osel){
    const __half* A  = g_MSG;
    const __half* Wh = (wsel == 0) ? g_W0h : (wsel == 1) ? g_W1h : g_W2h;
    __nv_bfloat16* out = gbuf16(osel);

    __shared__ __half Ash[2][128*ALD2];
    __shared__ __half Bsh[2][32*BLD];

    const int t = threadIdx.x;
    const int warp = t >> 5, lane = t & 31;
    const int wm = warp >> 2, wn = warp & 3;
    const int row0 = blockIdx.y*128, col0 = blockIdx.x*128;

    float acc[4][4][4];
    #pragma unroll
    for (int i=0;i<4;i++)
        #pragma unroll
        for (int j=0;j<4;j++)
            #pragma unroll
            for (int q=0;q<4;q++) acc[i][j][q]=0.f;

    auto prefetch = [&](int ks, int buf){
        const int k0 = ks*32;
        // A: 128 rows x 32 halves (64B) = 512 x 16B chunks
        #pragma unroll
        for (int s=0;s<2;s++){
            int c = t + s*256;
            int r = c >> 2, seg = c & 3;
            int gr = row0 + r;
            uint32_t dst = sptr(&Ash[buf][r*ALD2 + seg*8]);
            const void* src = A + (size_t)gr*K + k0 + seg*8;
            cpa16(dst, src, (gr < NN) ? 16 : 0);
        }
        // B: 32 rows x 128 halves (256B) = 512 x 16B chunks
        #pragma unroll
        for (int s=0;s<2;s++){
            int c = t + s*256;
            int r = c >> 4, seg = c & 15;
            uint32_t dst = sptr(&Bsh[buf][r*BLD + seg*8]);
            const void* src = Wh + (size_t)(k0 + r)*HID + col0 + seg*8;
            cpa16(dst, src, 16);
        }
    };

    auto compute = [&](int buf){
        #pragma unroll
        for (int h=0; h<2; h++){
            const int arow = wm*64 + (lane & 15);
            const int acol = h*16 + (lane >> 4)*8;
            uint32_t aA = sptr(&Ash[buf][0]) + (uint32_t)((arow*ALD2 + acol)*2);
            const int brow = h*16 + (lane & 15);
            const int bcol = wn*32 + (lane >> 4)*8;
            uint32_t bA = sptr(&Bsh[buf][0]) + (uint32_t)((brow*BLD + bcol)*2);

            uint32_t A_[4][4], B[4][2];
            #pragma unroll
            for (int mi=0; mi<4; mi++)
                ldsm4(A_[mi][0],A_[mi][1],A_[mi][2],A_[mi][3], aA + (uint32_t)(mi*16*ALD2*2));
            #pragma unroll
            for (int np=0; np<2; np++)
                ldsm4t(B[2*np][0],B[2*np][1],B[2*np+1][0],B[2*np+1][1],
                       bA + (uint32_t)(np*16*2));
            #pragma unroll
            for (int mi=0; mi<4; mi++)
                #pragma unroll
                for (int ni=0; ni<4; ni++)
                    mma16816h(acc[mi][ni], A_[mi], B[ni][0], B[ni][1]);
        }
    };

    const int KS = K/32;
    prefetch(0, 0); CP_COMMIT();
    int buf = 0;
    for (int ks=0; ks<KS; ks++){
        CP_WAIT0();
        __syncthreads();
        if (ks+1 < KS){ prefetch(ks+1, buf^1); CP_COMMIT(); }
        compute(buf);
        buf ^= 1;
    }

    // epilogue: bias + relu, bf16 stores
    const int gid = lane >> 2, tig = lane & 3;
    #pragma unroll
    for (int ni=0; ni<4; ni++){
        int c = col0 + wn*32 + ni*8 + tig*2;
        float2 bb = *(const float2*)(bias + c);
        #pragma unroll
        for (int mi=0; mi<4; mi++){
            int r = row0 + wm*64 + mi*16 + gid;
            if (r < NN){
                __nv_bfloat162 o = __floats2bfloat162_rn(
                    fmaxf(acc[mi][ni][0] + bb.x, 0.f),
                    fmaxf(acc[mi][ni][1] + bb.y, 0.f));
                *(__nv_bfloat162*)(out + (size_t)r*HID + c) = o;
            }
            int r2 = r + 8;
            if (r2 < NN){
                __nv_bfloat162 o = __floats2bfloat162_rn(
                    fmaxf(acc[mi][ni][2] + bb.x, 0.f),
                    fmaxf(acc[mi][ni][3] + bb.y, 0.f));
                *(__nv_bfloat162*)(out + (size_t)r2*HID + c) = o;
            }
        }
    }
}

// ---------------- multipool (bf16 input) ----------------
__global__ void pool_kernel(const int* __restrict__ batches){
    const __nv_bfloat16* h = g_BA;   // final layer output
    __shared__ int idxs[SUBSZ];
    int t = threadIdx.x, b = blockIdx.x;
    if (t < SUBSZ) idxs[t] = batches[b*SUBSZ + t];
    __syncthreads();
    float s = 0.f, mn = 3.4e38f, mx = -3.4e38f;
    #pragma unroll 8
    for (int m = 0; m < SUBSZ; m++){
        float v = __bfloat162float(h[(size_t)idxs[m]*HID + t]);
        s += v; mn = fminf(mn, v); mx = fmaxf(mx, v);
    }
    float* z = g_Z + (size_t)b*4*HID;
    z[t]         = s;
    z[HID + t]   = s * (1.0f/SUBSZ);
    z[2*HID + t] = mn;
    z[3*HID + t] = mx;
}

// ---------------- readout + BCE ----------------
__global__ void zero_out(float* out){
    if (threadIdx.x == 0 && blockIdx.x == 0) out[0] = 0.f;
}

__global__ __launch_bounds__(256)
void readout8(const float* __restrict__ Wr1, const float* __restrict__ br1,
              const float* __restrict__ Wr2, const float* __restrict__ br2,
              const float* __restrict__ labels, float* out){
    const int b0 = blockIdx.x*8;
    __shared__ float z[8*4*HID];
    int t = threadIdx.x;
    const float4* zg = (const float4*)(g_Z + (size_t)b0*4*HID);
    #pragma unroll
    for (int j = t; j < 8*4*HID/4; j += 256)
        ((float4*)z)[j] = zg[j];
    __syncthreads();

    float bb = br1[t];
    float acc[8];
    #pragma unroll
    for (int j=0;j<8;j++) acc[j] = bb;

    #pragma unroll 8
    for (int k=0;k<4*HID;k++){
        float w = Wr1[(size_t)k*HID + t];
        #pragma unroll
        for (int j=0;j<8;j++) acc[j] += z[j*4*HID + k]*w;
    }
    __syncthreads();
    float wr2 = Wr2[t];
    #pragma unroll
    for (int j=0;j<8;j++) z[j*HID + t] = fmaxf(acc[j], 0.f)*wr2;
    __syncthreads();

    int w = t >> 5, lane = t & 31;
    float s = 0.f;
    #pragma unroll
    for (int q=0;q<8;q++) s += z[w*HID + lane + q*32];
    #pragma unroll
    for (int off=16; off>0; off>>=1) s += __shfl_xor_sync(0xffffffffu, s, off);
    if (lane == 0){
        float p = s + br2[0];
        float l = labels[b0 + w];
        float term = fmaxf(p, 0.f) - p*l + log1pf(expf(-fabsf(p)));
        atomicAdd(out, term * (1.0f/NSUB));
    }
}

// ---------------- launch ----------------
static cudaStream_t g_s2 = nullptr;
static cudaEvent_t  g_evFork = nullptr, g_evJoin = nullptr;

extern "C" void kernel_launch(void* const* d_in, const int* in_sizes, int n_in,
                              void* d_out, int out_size){
    const float* x       = (const float*)d_in[0];
    const int*   esrc    = (const int*)  d_in[1];
    const int*   edst    = (const int*)  d_in[2];
    const float* ew      = (const float*)d_in[3];
    const int*   batches = (const int*)  d_in[4];
    const float* labels  = (const float*)d_in[6];
    const float* W0      = (const float*)d_in[7];
    const float* b0      = (const float*)d_in[8];
    const float* W1      = (const float*)d_in[9];
    const float* b1      = (const float*)d_in[10];
    const float* W2      = (const float*)d_in[11];
    const float* b2      = (const float*)d_in[12];
    const float* eps     = (const float*)d_in[13];
    const float* Wr1     = (const float*)d_in[14];
    const float* br1     = (const float*)d_in[15];
    const float* Wr2     = (const float*)d_in[16];
    const float* br2     = (const float*)d_in[17];
    float* out = (float*)d_out;

    if (!g_s2){
        cudaStreamCreateWithFlags(&g_s2, cudaStreamNonBlocking);
        cudaEventCreateWithFlags(&g_evFork, cudaEventDisableTiming);
        cudaEventCreateWithFlags(&g_evJoin, cudaEventDisableTiming);
    }

    cudaEventRecord(g_evFork, 0);
    cudaStreamWaitEvent(g_s2, g_evFork, 0);

    // main stream: input prep + weight conversion
    build_h0<<<4096, 256>>>(x);
    scatter_batch<<<(MTOT+255)/256, 256>>>(batches);
    build_w0h<<<(K0*HID+255)/256, 256>>>(W0);
    build_wh<<<(HID*HID+255)/256, 256>>>(W1, 1);
    build_wh<<<(HID*HID+255)/256, 256>>>(W2, 2);

    // side stream: CSR build (by dst)
    zero_degcur<<<(NN+255)/256, 256, 0, g_s2>>>();
    hist_dst<<<(NE+255)/256, 256, 0, g_s2>>>(edst);
    scan_block<<<NBLK, SCAN_B, 0, g_s2>>>();
    scan_bsums<<<1, 256, 0, g_s2>>>();
    scan_add<<<NBLK, SCAN_B, 0, g_s2>>>();
    csr_scatter<<<(NE+255)/256, 256, 0, g_s2>>>(esrc, edst, ew);

    cudaEventRecord(g_evJoin, g_s2);
    cudaStreamWaitEvent(0, g_evJoin, 0);

    dim3 gemmGrid(2, (NN+127)/128);
    const int gatherGrid = (NN+3)/4;   // 4 nodes/block, 2 warps/node

    // layer 0
    csr_gather<<<gatherGrid, 256>>>(0, eps, 0, K0, 33, 40);
    gemm_mma<K0><<<gemmGrid, 256>>>(0, b0, 1);

    // layer 1
    csr_gather<<<gatherGrid, 256>>>(1, eps, 1, HID, 64, 64);
    gemm_mma<HID><<<gemmGrid, 256>>>(1, b1, 2);

    // layer 2
    csr_gather<<<gatherGrid, 256>>>(2, eps, 2, HID, 64, 64);
    gemm_mma<HID><<<gemmGrid, 256>>>(2, b2, 1);

    pool_kernel<<<NSUB, HID>>>(batches);
    zero_out<<<1, 32>>>(out);
    readout8<<<NSUB/8, 256>>>(Wr1, br1, Wr2, br2, labels, out);
}

// round 12
// speedup vs baseline: 1.1363x; 1.0732x over previous
#include <cuda_runtime.h>
#include <cuda_bf16.h>
#include <cuda_fp16.h>
#include <math.h>
#include <stdint.h>

#define NN    50000
#define FEAT  128
#define HID   256
#define K0    160        // layer-0 K (129 live -> 132 used) padded to 160
#define NE    800000
#define NSUB  512
#define SUBSZ 64
#define MTOT  (NSUB*SUBSZ)

#define SCAN_B 256
#define NBLK   ((NN + SCAN_B - 1) / SCAN_B)   // 196

// ---------------- scratch (device globals; no allocation allowed) ----------------
__device__ __align__(16) __half         g_MSG[NN*HID];   // fp16 GEMM A (160-col view for L0)
__device__ __align__(16) __nv_bfloat16  g_B0 [NN*K0];    // bf16 h0
__device__ __align__(16) __nv_bfloat16  g_BA [NN*HID];   // bf16 h (layers)
__device__ __align__(16) __nv_bfloat16  g_BB [NN*HID];
__device__ __align__(16) __half         g_W0h[K0*HID];   // fp16 zero-padded W0
__device__ __align__(16) __half         g_W1h[HID*HID];
__device__ __align__(16) __half         g_W2h[HID*HID];
__device__ __align__(16) float          g_Z  [NSUB*4*HID];
// CSR scratch
__device__ int   g_deg [NN];
__device__ int   g_cur [NN];
__device__ int   g_off [NN+1];
__device__ int   g_bsum[NBLK];
__device__ __align__(8) int2 g_cpak[NE];    // packed (src, w_bits)

__device__ __forceinline__ __nv_bfloat16* gbuf16(int id){
    switch(id){
        case 0: return g_B0;
        case 1: return g_BA;
        default: return g_BB;
    }
}

// ---------------- setup ----------------
__global__ void build_h0(const float* __restrict__ x){
    int idx = blockIdx.x*blockDim.x + threadIdx.x;
    const int total = NN*K0;
    for (; idx < total; idx += gridDim.x*blockDim.x){
        int i = idx / K0;
        int c = idx - i*K0;
        g_B0[idx] = (c < FEAT) ? __float2bfloat16(x[i*FEAT + c]) : __float2bfloat16(0.f);
    }
}

__global__ void scatter_batch(const int* __restrict__ batches){
    int m = blockIdx.x*blockDim.x + threadIdx.x;
    if (m < MTOT) g_B0[(size_t)batches[m]*K0 + FEAT] = __float2bfloat16(1.0f);
}

__global__ void build_w0h(const float* __restrict__ W0){
    int idx = blockIdx.x*blockDim.x + threadIdx.x;
    if (idx < K0*HID){
        int r = idx / HID;
        int c = idx - r*HID;
        g_W0h[idx] = (r < FEAT+1) ? __float2half(W0[r*HID + c]) : __float2half(0.f);
    }
}

__global__ void build_wh(const float* __restrict__ W, int sel){
    __half* dst = (sel == 1) ? g_W1h : g_W2h;
    int i = blockIdx.x*blockDim.x + threadIdx.x;
    if (i < HID*HID) dst[i] = __float2half(W[i]);
}

// ---------------- CSR build ----------------
__global__ void zero_degcur(){
    int i = blockIdx.x*blockDim.x + threadIdx.x;
    if (i < NN){ g_deg[i] = 0; g_cur[i] = 0; }
}

__global__ void hist_dst(const int* __restrict__ dst){
    int e = blockIdx.x*blockDim.x + threadIdx.x;
    if (e < NE) atomicAdd(&g_deg[dst[e]], 1);
}

__global__ void scan_block(){
    __shared__ int sh[SCAN_B];
    int i = blockIdx.x*SCAN_B + threadIdx.x;
    int v = (i < NN) ? g_deg[i] : 0;
    sh[threadIdx.x] = v;
    __syncthreads();
    #pragma unroll
    for (int off = 1; off < SCAN_B; off <<= 1){
        int add = (threadIdx.x >= off) ? sh[threadIdx.x - off] : 0;
        __syncthreads();
        sh[threadIdx.x] += add;
        __syncthreads();
    }
    if (i < NN) g_off[i] = sh[threadIdx.x] - v;
    if (threadIdx.x == SCAN_B-1) g_bsum[blockIdx.x] = sh[SCAN_B-1];
}

__global__ void scan_bsums(){
    __shared__ int sh[256];
    int t = threadIdx.x;
    int v = (t < NBLK) ? g_bsum[t] : 0;
    sh[t] = v;
    __syncthreads();
    #pragma unroll
    for (int off = 1; off < 256; off <<= 1){
        int add = (t >= off) ? sh[t - off] : 0;
        __syncthreads();
        sh[t] += add;
        __syncthreads();
    }
    if (t < NBLK) g_bsum[t] = sh[t] - v;
}

__global__ void scan_add(){
    int i = blockIdx.x*SCAN_B + threadIdx.x;
    if (i < NN) g_off[i] += g_bsum[blockIdx.x];
    if (i == 0) g_off[NN] = NE;
}

__global__ void csr_scatter(const int* __restrict__ src, const int* __restrict__ dst,
                            const float* __restrict__ ew){
    int e = blockIdx.x*blockDim.x + threadIdx.x;
    if (e < NE){
        int d = dst[e];
        int pos = g_off[d] + atomicAdd(&g_cur[d], 1);
        g_cpak[pos] = make_int2(src[e], __float_as_int(ew[e]));
    }
}

// ---------------- gather (bf16 inputs, f32 accumulate, fp16 output) ----------------
__device__ __forceinline__ void facc(float4& a, float w, uint2 u){
    float2 f0 = __bfloat1622float2(*(__nv_bfloat162*)&u.x);
    float2 f1 = __bfloat1622float2(*(__nv_bfloat162*)&u.y);
    a.x += w*f0.x; a.y += w*f0.y; a.z += w*f1.x; a.w += w*f1.y;
}
__device__ __forceinline__ uint2 f4toh4(float4 a){
    __half2 lo = __floats2half2_rn(a.x, a.y);
    __half2 hi = __floats2half2_rn(a.z, a.w);
    return make_uint2(*(uint32_t*)&lo, *(uint32_t*)&hi);
}

__global__ __launch_bounds__(256)
void csr_gather(int hsel, const float* __restrict__ eps, int ei, int ld, int w4r, int w4p){
    const __nv_bfloat16* h = gbuf16(hsel);
    int n = blockIdx.x*8 + (threadIdx.x >> 5);
    if (n >= NN) return;
    int lane = threadIdx.x & 31;
    int s0 = g_off[n], s1 = g_off[n+1];

    const bool a0 = (lane      < w4r);
    const bool a1 = (lane + 32 < w4r);
    float4 acc0 = make_float4(0.f,0.f,0.f,0.f);
    float4 acc1 = make_float4(0.f,0.f,0.f,0.f);

    int e = s0;
    for (; e + 4 <= s1; e += 4){
        int2 p[4];
        #pragma unroll
        for (int j=0;j<4;j++)
            p[j] = __ldg(&g_cpak[e+j]);
        uint2 u0[4], u1[4];
        #pragma unroll
        for (int j=0;j<4;j++){
            const uint2* hs = (const uint2*)(h + (size_t)p[j].x*ld);
            if (a0) u0[j] = __ldg(&hs[lane]);
            if (a1) u1[j] = __ldg(&hs[lane+32]);
        }
        #pragma unroll
        for (int j=0;j<4;j++){
            float w = __int_as_float(p[j].y);
            if (a0) facc(acc0, w, u0[j]);
            if (a1) facc(acc1, w, u1[j]);
        }
    }
    for (; e < s1; e++){
        int2 p = __ldg(&g_cpak[e]);
        float w = __int_as_float(p.y);
        const uint2* hs = (const uint2*)(h + (size_t)p.x*ld);
        if (a0){ uint2 u = __ldg(&hs[lane]);    facc(acc0, w, u); }
        if (a1){ uint2 u = __ldg(&hs[lane+32]); facc(acc1, w, u); }
    }

    const float ep = 1.0f + eps[ei];
    const uint2* hn = (const uint2*)(h + (size_t)n*ld);
    uint2* mrow = (uint2*)(g_MSG + (size_t)n*ld);
    if (a0){
        uint2 u = __ldg(&hn[lane]);
        facc(acc0, ep, u);
        mrow[lane] = f4toh4(acc0);
    }
    if (a1){
        uint2 u = __ldg(&hn[lane+32]);
        facc(acc1, ep, u);
        mrow[lane+32] = f4toh4(acc1);
    } else if (lane + 32 < w4p){
        mrow[lane+32] = make_uint2(0u, 0u);
    }
}

// ---------------- tensor-core GIN GEMM: outb16 = relu(MSG @ W + b) ------
// pure fp16, BK=32, cp.async double-buffered, 1 sync per kstep.
__device__ __forceinline__ uint32_t sptr(const void* p){
    return (uint32_t)__cvta_generic_to_shared(p);
}
__device__ __forceinline__ void cpa16(uint32_t smem, const void* g, int nbytes){
    asm volatile("cp.async.cg.shared.global [%0], [%1], 16, %2;"
                 :: "r"(smem), "l"(g), "r"(nbytes) : "memory");
}
#define CP_COMMIT() asm volatile("cp.async.commit_group;" ::: "memory")
#define CP_WAIT0()  asm volatile("cp.async.wait_group 0;" ::: "memory")

__device__ __forceinline__ void ldsm4(uint32_t& r0,uint32_t& r1,uint32_t& r2,uint32_t& r3, uint32_t a){
    asm volatile("ldmatrix.sync.aligned.m8n8.x4.shared.b16 {%0,%1,%2,%3},[%4];"
                 : "=r"(r0),"=r"(r1),"=r"(r2),"=r"(r3) : "r"(a));
}
__device__ __forceinline__ void ldsm4t(uint32_t& r0,uint32_t& r1,uint32_t& r2,uint32_t& r3, uint32_t a){
    asm volatile("ldmatrix.sync.aligned.m8n8.x4.trans.shared.b16 {%0,%1,%2,%3},[%4];"
                 : "=r"(r0),"=r"(r1),"=r"(r2),"=r"(r3) : "r"(a));
}
__device__ __forceinline__ void mma16816h(float* c, const uint32_t* a, uint32_t b0, uint32_t b1){
    asm volatile("mma.sync.aligned.m16n8k16.row.col.f32.f16.f16.f32 "
                 "{%0,%1,%2,%3},{%4,%5,%6,%7},{%8,%9},{%0,%1,%2,%3};"
                 : "+f"(c[0]),"+f"(c[1]),"+f"(c[2]),"+f"(c[3])
                 : "r"(a[0]),"r"(a[1]),"r"(a[2]),"r"(a[3]),"r"(b0),"r"(b1));
}

#define ALD2 40    // Ash row stride (halves), BK=32 + pad 8
#define BLD  136   // Bsh row stride (halves)

template<int K>
__global__ __launch_bounds__(256)
void gemm_mma(int wsel, const float* __restrict__ bias, int osel){
    const __half* A  = g_MSG;
    const __half* Wh = (wsel == 0) ? g_W0h : (wsel == 1) ? g_W1h : g_W2h;
    __nv_bfloat16* out = gbuf16(osel);

    __shared__ __half Ash[2][128*ALD2];
    __shared__ __half Bsh[2][32*BLD];

    const int t = threadIdx.x;
    const int warp = t >> 5, lane = t & 31;
    const int wm = warp >> 2, wn = warp & 3;
    const int row0 = blockIdx.y*128, col0 = blockIdx.x*128;

    float acc[4][4][4];
    #pragma unroll
    for (int i=0;i<4;i++)
        #pragma unroll
        for (int j=0;j<4;j++)
            #pragma unroll
            for (int q=0;q<4;q++) acc[i][j][q]=0.f;

    auto prefetch = [&](int ks, int buf){
        const int k0 = ks*32;
        // A: 128 rows x 32 halves (64B) = 512 x 16B chunks
        #pragma unroll
        for (int s=0;s<2;s++){
            int c = t + s*256;
            int r = c >> 2, seg = c & 3;
            int gr = row0 + r;
            uint32_t dst = sptr(&Ash[buf][r*ALD2 + seg*8]);
            const void* src = A + (size_t)gr*K + k0 + seg*8;
            cpa16(dst, src, (gr < NN) ? 16 : 0);
        }
        // B: 32 rows x 128 halves (256B) = 512 x 16B chunks
        #pragma unroll
        for (int s=0;s<2;s++){
            int c = t + s*256;
            int r = c >> 4, seg = c & 15;
            uint32_t dst = sptr(&Bsh[buf][r*BLD + seg*8]);
            const void* src = Wh + (size_t)(k0 + r)*HID + col0 + seg*8;
            cpa16(dst, src, 16);
        }
    };

    auto compute = [&](int buf){
        #pragma unroll
        for (int h=0; h<2; h++){
            const int arow = wm*64 + (lane & 15);
            const int acol = h*16 + (lane >> 4)*8;
            uint32_t aA = sptr(&Ash[buf][0]) + (uint32_t)((arow*ALD2 + acol)*2);
            const int brow = h*16 + (lane & 15);
            const int bcol = wn*32 + (lane >> 4)*8;
            uint32_t bA = sptr(&Bsh[buf][0]) + (uint32_t)((brow*BLD + bcol)*2);

            uint32_t A_[4][4], B[4][2];
            #pragma unroll
            for (int mi=0; mi<4; mi++)
                ldsm4(A_[mi][0],A_[mi][1],A_[mi][2],A_[mi][3], aA + (uint32_t)(mi*16*ALD2*2));
            #pragma unroll
            for (int np=0; np<2; np++)
                ldsm4t(B[2*np][0],B[2*np][1],B[2*np+1][0],B[2*np+1][1],
                       bA + (uint32_t)(np*16*2));
            #pragma unroll
            for (int mi=0; mi<4; mi++)
                #pragma unroll
                for (int ni=0; ni<4; ni++)
                    mma16816h(acc[mi][ni], A_[mi], B[ni][0], B[ni][1]);
        }
    };

    const int KS = K/32;
    prefetch(0, 0); CP_COMMIT();
    int buf = 0;
    for (int ks=0; ks<KS; ks++){
        CP_WAIT0();
        __syncthreads();
        if (ks+1 < KS){ prefetch(ks+1, buf^1); CP_COMMIT(); }
        compute(buf);
        buf ^= 1;
    }

    // epilogue: bias + relu, bf16 stores
    const int gid = lane >> 2, tig = lane & 3;
    #pragma unroll
    for (int ni=0; ni<4; ni++){
        int c = col0 + wn*32 + ni*8 + tig*2;
        float2 bb = *(const float2*)(bias + c);
        #pragma unroll
        for (int mi=0; mi<4; mi++){
            int r = row0 + wm*64 + mi*16 + gid;
            if (r < NN){
                __nv_bfloat162 o = __floats2bfloat162_rn(
                    fmaxf(acc[mi][ni][0] + bb.x, 0.f),
                    fmaxf(acc[mi][ni][1] + bb.y, 0.f));
                *(__nv_bfloat162*)(out + (size_t)r*HID + c) = o;
            }
            int r2 = r + 8;
            if (r2 < NN){
                __nv_bfloat162 o = __floats2bfloat162_rn(
                    fmaxf(acc[mi][ni][2] + bb.x, 0.f),
                    fmaxf(acc[mi][ni][3] + bb.y, 0.f));
                *(__nv_bfloat162*)(out + (size_t)r2*HID + c) = o;
            }
        }
    }
}

// ---------------- multipool (bf16 input) + output zeroing ----------------
__global__ void pool_kernel(const int* __restrict__ batches, float* out){
    const __nv_bfloat16* h = g_BA;   // final layer output
    __shared__ int idxs[SUBSZ];
    int t = threadIdx.x, b = blockIdx.x;
    if (b == 0 && t == 0) out[0] = 0.f;   // pool precedes readout; race-free
    if (t < SUBSZ) idxs[t] = batches[b*SUBSZ + t];
    __syncthreads();
    float s = 0.f, mn = 3.4e38f, mx = -3.4e38f;
    #pragma unroll 8
    for (int m = 0; m < SUBSZ; m++){
        float v = __bfloat162float(h[(size_t)idxs[m]*HID + t]);
        s += v; mn = fminf(mn, v); mx = fmaxf(mx, v);
    }
    float* z = g_Z + (size_t)b*4*HID;
    z[t]         = s;
    z[HID + t]   = s * (1.0f/SUBSZ);
    z[2*HID + t] = mn;
    z[3*HID + t] = mx;
}

// ---------------- readout + BCE ----------------
__global__ __launch_bounds__(256)
void readout8(const float* __restrict__ Wr1, const float* __restrict__ br1,
              const float* __restrict__ Wr2, const float* __restrict__ br2,
              const float* __restrict__ labels, float* out){
    const int b0 = blockIdx.x*8;
    __shared__ float z[8*4*HID];
    int t = threadIdx.x;
    const float4* zg = (const float4*)(g_Z + (size_t)b0*4*HID);
    #pragma unroll
    for (int j = t; j < 8*4*HID/4; j += 256)
        ((float4*)z)[j] = zg[j];
    __syncthreads();

    float bb = br1[t];
    float acc[8];
    #pragma unroll
    for (int j=0;j<8;j++) acc[j] = bb;

    #pragma unroll 8
    for (int k=0;k<4*HID;k++){
        float w = Wr1[(size_t)k*HID + t];
        #pragma unroll
        for (int j=0;j<8;j++) acc[j] += z[j*4*HID + k]*w;
    }
    __syncthreads();
    float wr2 = Wr2[t];
    #pragma unroll
    for (int j=0;j<8;j++) z[j*HID + t] = fmaxf(acc[j], 0.f)*wr2;
    __syncthreads();

    int w = t >> 5, lane = t & 31;
    float s = 0.f;
    #pragma unroll
    for (int q=0;q<8;q++) s += z[w*HID + lane + q*32];
    #pragma unroll
    for (int off=16; off>0; off>>=1) s += __shfl_xor_sync(0xffffffffu, s, off);
    if (lane == 0){
        float p = s + br2[0];
        float l = labels[b0 + w];
        float term = fmaxf(p, 0.f) - p*l + log1pf(expf(-fabsf(p)));
        atomicAdd(out, term * (1.0f/NSUB));
    }
}

// ---------------- launch ----------------
static cudaStream_t g_s2 = nullptr;
static cudaEvent_t  g_evFork = nullptr, g_evJoin = nullptr;

extern "C" void kernel_launch(void* const* d_in, const int* in_sizes, int n_in,
                              void* d_out, int out_size){
    const float* x       = (const float*)d_in[0];
    const int*   esrc    = (const int*)  d_in[1];
    const int*   edst    = (const int*)  d_in[2];
    const float* ew      = (const float*)d_in[3];
    const int*   batches = (const int*)  d_in[4];
    const float* labels  = (const float*)d_in[6];
    const float* W0      = (const float*)d_in[7];
    const float* b0      = (const float*)d_in[8];
    const float* W1      = (const float*)d_in[9];
    const float* b1      = (const float*)d_in[10];
    const float* W2      = (const float*)d_in[11];
    const float* b2      = (const float*)d_in[12];
    const float* eps     = (const float*)d_in[13];
    const float* Wr1     = (const float*)d_in[14];
    const float* br1     = (const float*)d_in[15];
    const float* Wr2     = (const float*)d_in[16];
    const float* br2     = (const float*)d_in[17];
    float* out = (float*)d_out;

    if (!g_s2){
        cudaStreamCreateWithFlags(&g_s2, cudaStreamNonBlocking);
        cudaEventCreateWithFlags(&g_evFork, cudaEventDisableTiming);
        cudaEventCreateWithFlags(&g_evJoin, cudaEventDisableTiming);
    }

    cudaEventRecord(g_evFork, 0);
    cudaStreamWaitEvent(g_s2, g_evFork, 0);

    // main stream: input prep + weight conversion
    build_h0<<<4096, 256>>>(x);
    scatter_batch<<<(MTOT+255)/256, 256>>>(batches);
    build_w0h<<<(K0*HID+255)/256, 256>>>(W0);
    build_wh<<<(HID*HID+255)/256, 256>>>(W1, 1);
    build_wh<<<(HID*HID+255)/256, 256>>>(W2, 2);

    // side stream: CSR build (by dst)
    zero_degcur<<<(NN+255)/256, 256, 0, g_s2>>>();
    hist_dst<<<(NE+255)/256, 256, 0, g_s2>>>(edst);
    scan_block<<<NBLK, SCAN_B, 0, g_s2>>>();
    scan_bsums<<<1, 256, 0, g_s2>>>();
    scan_add<<<NBLK, SCAN_B, 0, g_s2>>>();
    csr_scatter<<<(NE+255)/256, 256, 0, g_s2>>>(esrc, edst, ew);

    cudaEventRecord(g_evJoin, g_s2);
    cudaStreamWaitEvent(0, g_evJoin, 0);

    dim3 gemmGrid(2, (NN+127)/128);
    const int gatherGrid = (NN+7)/8;

    // layer 0
    csr_gather<<<gatherGrid, 256>>>(0, eps, 0, K0, 33, 40);
    gemm_mma<K0><<<gemmGrid, 256>>>(0, b0, 1);

    // layer 1
    csr_gather<<<gatherGrid, 256>>>(1, eps, 1, HID, 64, 64);
    gemm_mma<HID><<<gemmGrid, 256>>>(1, b1, 2);

    // layer 2
    csr_gather<<<gatherGrid, 256>>>(2, eps, 2, HID, 64, 64);
    gemm_mma<HID><<<gemmGrid, 256>>>(2, b2, 1);

    pool_kernel<<<NSUB, HID>>>(batches, out);
    readout8<<<NSUB/8, 256>>>(Wr1, br1, Wr2, br2, labels, out);
}